// round 9
// baseline (speedup 1.0000x reference)
#include <cuda_runtime.h>

#define NN 50000
#define EE 800000
#define FF 128
#define SBLK 256
#define NBLK ((NN + SBLK - 1) / SBLK)   // 196

// ---------------- scratch (device globals; sanctioned scratch mechanism) ---------
__device__ int   g_is64;
__device__ int   g_deg[NN];
__device__ int   g_off[NN];
__device__ int   g_cur[NN];
__device__ float g_dinv[NN];
__device__ int   g_csr[EE];
__device__ float g_hs[NN * FF];
__device__ float g_agg[NN * FF];
__device__ float g_stats1[2 * FF];
__device__ float g_stats2[2 * FF];
__device__ int   g_bsum[NBLK];

// ---------------- f32x2 helpers ---------------------------------------------------
__device__ __forceinline__ unsigned long long fma2(unsigned long long a,
                                                   unsigned long long b,
                                                   unsigned long long c) {
    unsigned long long d;
    asm("fma.rn.f32x2 %0, %1, %2, %3;" : "=l"(d) : "l"(a), "l"(b), "l"(c));
    return d;
}
__device__ __forceinline__ unsigned long long pack2(float x) {
    unsigned long long r;
    asm("mov.b64 %0, {%1, %1};" : "=l"(r) : "f"(x));
    return r;
}
__device__ __forceinline__ float2 unpack2(unsigned long long v) {
    float2 f;
    asm("mov.b64 {%0, %1}, %2;" : "=f"(f.x), "=f"(f.y) : "l"(v));
    return f;
}

// ---------------- init: zero deg/stats + dtype detect ----------------------------
__global__ __launch_bounds__(SBLK) void k_init(const unsigned int* __restrict__ p) {
    int gi = blockIdx.x * SBLK + threadIdx.x;
    if (gi < NN) g_deg[gi] = 0;
    if (gi < 2 * FF) { g_stats1[gi] = 0.f; g_stats2[gi] = 0.f; }
    if (blockIdx.x == 0) {
        __shared__ int any;
        if (threadIdx.x == 0) any = 0;
        __syncthreads();
        if (p[2 * threadIdx.x + 1] != 0u) atomicOr(&any, 1);
        __syncthreads();
        if (threadIdx.x == 0) g_is64 = !any;
    }
}

// degree count (32-bit low-word loads; node ids < 2^31)
__global__ __launch_bounds__(256) void k_count(const int* __restrict__ p32) {
    int e = blockIdx.x * blockDim.x + threadIdx.x;
    if (e >= EE) return;
    int dst = g_is64 ? p32[2 * (EE + e)] : p32[EE + e];
    atomicAdd(&g_deg[dst], 1);
}

// per-scan-block sums (full-chip parallel)
__global__ __launch_bounds__(SBLK) void k_bsum() {
    __shared__ int sh[SBLK];
    int i = blockIdx.x * SBLK + threadIdx.x;
    sh[threadIdx.x] = (i < NN) ? g_deg[i] : 0;
    __syncthreads();
#pragma unroll
    for (int off = SBLK / 2; off > 0; off >>= 1) {
        if (threadIdx.x < off) sh[threadIdx.x] += sh[threadIdx.x + off];
        __syncthreads();
    }
    if (threadIdx.x == 0) g_bsum[blockIdx.x] = sh[0];
}

// offsets: block base = warp-reduce of g_bsum prefix; also writes g_dinv
__global__ __launch_bounds__(SBLK) void k_offsets() {
    __shared__ int sh[SBLK];
    __shared__ int sbase;
    int tid = threadIdx.x;
    if (tid == 0) sbase = 0;
    __syncthreads();
    int v = (tid < blockIdx.x) ? g_bsum[tid] : 0;   // NBLK=196 <= 256
#pragma unroll
    for (int o = 16; o > 0; o >>= 1) v += __shfl_down_sync(0xffffffffu, v, o);
    if ((tid & 31) == 0) atomicAdd(&sbase, v);

    int i = blockIdx.x * SBLK + tid;
    int d = (i < NN) ? g_deg[i] : 0;
    sh[tid] = d;
    __syncthreads();
#pragma unroll
    for (int off = 1; off < SBLK; off <<= 1) {
        int w = (tid >= off) ? sh[tid - off] : 0;
        __syncthreads();
        sh[tid] += w;
        __syncthreads();
    }
    if (i < NN) {
        int o = sbase + sh[tid] - d;   // exclusive
        g_off[i] = o;
        g_cur[i] = o;
        g_dinv[i] = rsqrtf((float)(d + 1));
    }
}

__global__ __launch_bounds__(256) void k_fill(const int* __restrict__ p32) {
    int e = blockIdx.x * blockDim.x + threadIdx.x;
    if (e >= EE) return;
    int src, dst;
    if (g_is64) {
        src = p32[2 * e];
        dst = p32[2 * (EE + e)];
    } else {
        src = p32[e];
        dst = p32[EE + e];
    }
    int pos = atomicAdd(&g_cur[dst], 1);
    g_csr[pos] = src;
}

// ---------------- GEMM: g_hs = f(A) @ W  (no dinv — moved to k_agg) --------------
// 96x128 tile/block (521 blocks), 256 threads, 6x8 micro-tile, f32x2 FMAs.
// smem 67.6KB, regs<=85 -> 3 blocks/SM = 24 warps. W staged in 32-k chunks.
#define TM 96
#define KCH 32
#define APAD 98
#define GEMM_SMEM (((KCH * FF) + (FF * APAD) + 2 * FF) * 4)

__global__ __launch_bounds__(256, 3) void k_gemm(const float* __restrict__ A,
                                                 const float* __restrict__ W,
                                                 const float* __restrict__ stats,
                                                 const float* __restrict__ gam,
                                                 const float* __restrict__ bet,
                                                 const float* __restrict__ aw) {
    extern __shared__ float sm[];
    float* Ws  = sm;                              // [KCH][128] chunk
    float* As  = sm + KCH * FF;                   // [k*APAD + r], full K
    float* ssc = sm + KCH * FF + FF * APAD;       // [128] BN scale
    float* sof = ssc + FF;                        // [128] BN offset
    int tid = threadIdx.x;
    int row0 = blockIdx.x * TM;
    bool fuse = (stats != nullptr);
    float a1 = 0.f;

    if (fuse) {
        if (tid < FF) {
            const float invN = 1.f / (float)NN;
            float mu  = stats[tid] * invN;
            float var = stats[FF + tid] * invN - mu * mu;
            float inv = rsqrtf(var + 1e-5f);
            float sc  = gam[tid] * inv;
            ssc[tid] = sc;
            sof[tid] = bet[tid] - mu * sc;
        }
        a1 = __ldg(&aw[0]);
        __syncthreads();
    }

    if (fuse) {
        for (int i = tid; i < TM * FF; i += 256) {
            int r = i >> 7, k = i & 127;
            int gr = row0 + r;
            float v = 0.f;
            if (gr < NN) {
                float t = A[gr * FF + k] * ssc[k] + sof[k];
                v = (t >= 0.f) ? t : a1 * t;
            }
            As[k * APAD + r] = v;
        }
    } else {
        for (int i = tid; i < TM * FF; i += 256) {
            int r = i >> 7, k = i & 127;
            int gr = row0 + r;
            As[k * APAD + r] = (gr < NN) ? A[gr * FF + k] : 0.f;
        }
    }

    int tx = tid & 15, ty = tid >> 4;   // 16 x 16
    int i0 = ty * 6, j0 = tx * 8;

    unsigned long long acc[6][4];
#pragma unroll
    for (int r = 0; r < 6; r++)
#pragma unroll
        for (int c = 0; c < 4; c++) acc[r][c] = 0ull;

    for (int kc = 0; kc < FF / KCH; kc++) {
        __syncthreads();   // Ws free to overwrite (covers As staging on kc=0)
        {
            const float4* Wg = (const float4*)(W + kc * KCH * FF);
            float4* Wv = (float4*)Ws;
            for (int i = tid; i < KCH * FF / 4; i += 256) Wv[i] = Wg[i];
        }
        __syncthreads();
#pragma unroll 2
        for (int k = 0; k < KCH; k++) {
            const float* wrow = Ws + k * FF + j0;
            ulonglong2 wA = *(const ulonglong2*)(wrow);      // LDS.128
            ulonglong2 wB = *(const ulonglong2*)(wrow + 4);  // LDS.128
            const float* ar = As + (kc * KCH + k) * APAD + i0;
            float2 p0 = *(const float2*)(ar + 0);            // LDS.64
            float2 p1 = *(const float2*)(ar + 2);
            float2 p2 = *(const float2*)(ar + 4);
            float av[6] = {p0.x, p0.y, p1.x, p1.y, p2.x, p2.y};
#pragma unroll
            for (int r = 0; r < 6; r++) {
                unsigned long long aa = pack2(av[r]);
                acc[r][0] = fma2(aa, wA.x, acc[r][0]);
                acc[r][1] = fma2(aa, wA.y, acc[r][1]);
                acc[r][2] = fma2(aa, wB.x, acc[r][2]);
                acc[r][3] = fma2(aa, wB.y, acc[r][3]);
            }
        }
    }

#pragma unroll
    for (int r = 0; r < 6; r++) {
        int gr = row0 + i0 + r;
        if (gr < NN) {
            float2 p;
            float4 o0, o1;
            p = unpack2(acc[r][0]); o0.x = p.x; o0.y = p.y;
            p = unpack2(acc[r][1]); o0.z = p.x; o0.w = p.y;
            p = unpack2(acc[r][2]); o1.x = p.x; o1.y = p.y;
            p = unpack2(acc[r][3]); o1.z = p.x; o1.w = p.y;
            float4* dst = (float4*)(g_hs + gr * FF + j0);
            dst[0] = o0;
            dst[1] = o1;
        }
    }
}

// ---------------- aggregation (applies ALL dinv scaling; 4-way unrolled) ----------
// agg[dst] = dinv[dst] * ( h[dst]*dinv[dst] + sum_src h[src]*dinv[src] )
__global__ __launch_bounds__(256) void k_agg() {
    int tid = threadIdx.x;
    int lane = tid & 31;
    int gw = (blockIdx.x * 256 + tid) >> 5;   // node id (1 warp per node)
    const float4* b = (const float4*)g_hs;
    float dself = __ldg(&g_dinv[gw]);
    float4 a0 = b[gw * 32 + lane];
    a0.x *= dself; a0.y *= dself; a0.z *= dself; a0.w *= dself;
    float4 a1 = {0.f, 0.f, 0.f, 0.f};
    float4 a2 = {0.f, 0.f, 0.f, 0.f};
    float4 a3 = {0.f, 0.f, 0.f, 0.f};
    int s = g_off[gw];
    int n = g_deg[gw];
    int e = s, end4 = s + (n & ~3);
    for (; e < end4; e += 4) {
        int s0 = __ldg(&g_csr[e + 0]);
        int s1 = __ldg(&g_csr[e + 1]);
        int s2 = __ldg(&g_csr[e + 2]);
        int s3 = __ldg(&g_csr[e + 3]);
        float d0 = __ldg(&g_dinv[s0]);
        float d1 = __ldg(&g_dinv[s1]);
        float d2 = __ldg(&g_dinv[s2]);
        float d3 = __ldg(&g_dinv[s3]);
        float4 v0 = b[s0 * 32 + lane];
        float4 v1 = b[s1 * 32 + lane];
        float4 v2 = b[s2 * 32 + lane];
        float4 v3 = b[s3 * 32 + lane];
        a0.x = fmaf(v0.x, d0, a0.x); a0.y = fmaf(v0.y, d0, a0.y);
        a0.z = fmaf(v0.z, d0, a0.z); a0.w = fmaf(v0.w, d0, a0.w);
        a1.x = fmaf(v1.x, d1, a1.x); a1.y = fmaf(v1.y, d1, a1.y);
        a1.z = fmaf(v1.z, d1, a1.z); a1.w = fmaf(v1.w, d1, a1.w);
        a2.x = fmaf(v2.x, d2, a2.x); a2.y = fmaf(v2.y, d2, a2.y);
        a2.z = fmaf(v2.z, d2, a2.z); a2.w = fmaf(v2.w, d2, a2.w);
        a3.x = fmaf(v3.x, d3, a3.x); a3.y = fmaf(v3.y, d3, a3.y);
        a3.z = fmaf(v3.z, d3, a3.z); a3.w = fmaf(v3.w, d3, a3.w);
    }
    for (; e < s + n; e++) {
        int s0 = __ldg(&g_csr[e]);
        float d0 = __ldg(&g_dinv[s0]);
        float4 v0 = b[s0 * 32 + lane];
        a0.x = fmaf(v0.x, d0, a0.x); a0.y = fmaf(v0.y, d0, a0.y);
        a0.z = fmaf(v0.z, d0, a0.z); a0.w = fmaf(v0.w, d0, a0.w);
    }
    a0.x += a1.x + a2.x + a3.x;
    a0.y += a1.y + a2.y + a3.y;
    a0.z += a1.z + a2.z + a3.z;
    a0.w += a1.w + a2.w + a3.w;
    a0.x *= dself; a0.y *= dself; a0.z *= dself; a0.w *= dself;
    ((float4*)g_agg)[gw * 32 + lane] = a0;
}

// column sums / sumsq (proven; 102K atomics over 256 addrs)
__global__ __launch_bounds__(128) void k_reduce(float* __restrict__ stats) {
    int col = threadIdx.x;  // blockDim = 128
    int r0 = blockIdx.x * 125;
    int r1 = min(r0 + 125, NN);
    float s = 0.f, q = 0.f;
    for (int r = r0; r < r1; r++) {
        float v = g_agg[r * FF + col];
        s += v;
        q += v * v;
    }
    atomicAdd(&stats[col], s);
    atomicAdd(&stats[FF + col], q);
}

// BatchNorm (biased var) + PReLU for the final layer
__global__ __launch_bounds__(256) void k_norm(const float* __restrict__ stats,
                                              const float* __restrict__ gam,
                                              const float* __restrict__ bet,
                                              const float* __restrict__ aw,
                                              float* __restrict__ out) {
    int idx = blockIdx.x * blockDim.x + threadIdx.x;
    int c = (idx & 31) * 4;
    float4 v = ((const float4*)g_agg)[idx];
    float a = __ldg(&aw[0]);
    float vv[4] = {v.x, v.y, v.z, v.w};
    float o[4];
    const float invN = 1.f / (float)NN;
#pragma unroll
    for (int j = 0; j < 4; j++) {
        float mu  = stats[c + j] * invN;
        float var = stats[FF + c + j] * invN - mu * mu;
        float inv = rsqrtf(var + 1e-5f);
        float sc  = gam[c + j] * inv;
        float of  = bet[c + j] - mu * sc;
        float t = vv[j] * sc + of;
        o[j] = (t >= 0.f) ? t : a * t;
    }
    float4 r = {o[0], o[1], o[2], o[3]};
    ((float4*)out)[idx] = r;
}

// ---------------- eager load + cached device ptrs + fork stream (static init) ----
namespace {
float* p_agg = nullptr;
float* p_st1 = nullptr;
float* p_st2 = nullptr;
cudaStream_t s_fork = nullptr;
cudaEvent_t  ev_in = nullptr, ev_gemm = nullptr;
struct HxEagerLoad {
    HxEagerLoad() {
        void* p = nullptr;
        cudaGetSymbolAddress(&p, g_hs);    // triggers full module load
        cudaGetSymbolAddress(&p, g_csr);
        cudaGetSymbolAddress((void**)&p_agg, g_agg);
        cudaGetSymbolAddress((void**)&p_st1, g_stats1);
        cudaGetSymbolAddress((void**)&p_st2, g_stats2);
        cudaFuncSetAttribute(k_gemm, cudaFuncAttributeMaxDynamicSharedMemorySize,
                             GEMM_SMEM);
        cudaStreamCreateWithFlags(&s_fork, cudaStreamNonBlocking);
        cudaEventCreateWithFlags(&ev_in, cudaEventDisableTiming);
        cudaEventCreateWithFlags(&ev_gemm, cudaEventDisableTiming);
    }
};
HxEagerLoad hx_eager_load_;
}  // namespace

// ---------------- launch ----------------------------------------------------------
extern "C" void kernel_launch(void* const* d_in, const int* in_sizes, int n_in,
                              void* d_out, int out_size) {
    const float* x   = (const float*)d_in[0];
    const int*   ei  = (const int*)d_in[1];
    const float* W1  = (const float*)d_in[2];
    const float* gm1 = (const float*)d_in[4];
    const float* be1 = (const float*)d_in[5];
    const float* a1  = (const float*)d_in[6];
    const float* W2  = (const float*)d_in[7];
    const float* gm2 = (const float*)d_in[9];
    const float* be2 = (const float*)d_in[10];
    const float* a2  = (const float*)d_in[11];
    float* out = (float*)d_out;

    const int gemm_blocks = (NN + TM - 1) / TM;   // 521
    const int agg_blocks  = (NN * 32) / 256;      // 6250 exact
    const int red_blocks  = (NN + 124) / 125;     // 400

    // fork point: GEMM1 depends only on upstream inputs, not the CSR build
    cudaEventRecord(ev_in, 0);
    cudaStreamWaitEvent(s_fork, ev_in, 0);

    // CSR build chain (default stream)                        launch idx
    k_init<<<NBLK, SBLK>>>((const unsigned int*)ei);           // 0
    k_count<<<(EE + 255) / 256, 256>>>(ei);                    // 1
    k_bsum<<<NBLK, SBLK>>>();                                  // 2
    k_offsets<<<NBLK, SBLK>>>();                               // 3
    k_fill<<<(EE + 255) / 256, 256>>>(ei);                     // 4

    // GEMM1 concurrent on forked stream
    k_gemm<<<gemm_blocks, 256, GEMM_SMEM, s_fork>>>(           // 5 (profiled)
        x, W1, nullptr, nullptr, nullptr, nullptr);
    cudaEventRecord(ev_gemm, s_fork);
    cudaStreamWaitEvent(0, ev_gemm, 0);

    // join: layer-1 aggregation onward (default stream)
    k_agg<<<agg_blocks, 256>>>();                              // 6
    k_reduce<<<red_blocks, 128>>>(p_st1);                      // 7
    k_gemm<<<gemm_blocks, 256, GEMM_SMEM>>>(p_agg, W2,         // 8 (BN1+PReLU fused)
                                            p_st1, gm1, be1, a1);
    k_agg<<<agg_blocks, 256>>>();                              // 9
    k_reduce<<<red_blocks, 128>>>(p_st2);                      // 10
    k_norm<<<agg_blocks, 256>>>(p_st2, gm2, be2, a2, out);     // 11
}

// round 10
// speedup vs baseline: 1.0774x; 1.0774x over previous
#include <cuda_runtime.h>

#define NN 50000
#define EE 800000
#define FF 128
#define SBLK 256
#define NBLK ((NN + SBLK - 1) / SBLK)   // 196

// ---------------- scratch (device globals; sanctioned scratch mechanism) ---------
__device__ int   g_is64;
__device__ int   g_deg[NN];
__device__ int   g_off[NN];
__device__ int   g_cur[NN];
__device__ float g_dinv[NN];
__device__ int   g_csr[EE];
__device__ float g_hs[NN * FF];
__device__ float g_agg[NN * FF];
__device__ float g_stats1[2 * FF];
__device__ float g_stats2[2 * FF];
__device__ int   g_bsum[NBLK];

// ---------------- f32x2 helpers ---------------------------------------------------
__device__ __forceinline__ unsigned long long fma2(unsigned long long a,
                                                   unsigned long long b,
                                                   unsigned long long c) {
    unsigned long long d;
    asm("fma.rn.f32x2 %0, %1, %2, %3;" : "=l"(d) : "l"(a), "l"(b), "l"(c));
    return d;
}
__device__ __forceinline__ unsigned long long pack2(float x) {
    unsigned long long r;
    asm("mov.b64 %0, {%1, %1};" : "=l"(r) : "f"(x));
    return r;
}
__device__ __forceinline__ float2 unpack2(unsigned long long v) {
    float2 f;
    asm("mov.b64 {%0, %1}, %2;" : "=f"(f.x), "=f"(f.y) : "l"(v));
    return f;
}

// ---------------- init: zero deg/stats + dtype detect ----------------------------
__global__ __launch_bounds__(SBLK) void k_init(const unsigned int* __restrict__ p) {
    int gi = blockIdx.x * SBLK + threadIdx.x;
    if (gi < NN) g_deg[gi] = 0;
    if (gi < 2 * FF) { g_stats1[gi] = 0.f; g_stats2[gi] = 0.f; }
    if (blockIdx.x == 0) {
        __shared__ int any;
        if (threadIdx.x == 0) any = 0;
        __syncthreads();
        if (p[2 * threadIdx.x + 1] != 0u) atomicOr(&any, 1);
        __syncthreads();
        if (threadIdx.x == 0) g_is64 = !any;
    }
}

// degree count (32-bit low-word loads; node ids < 2^31)
__global__ __launch_bounds__(256) void k_count(const int* __restrict__ p32) {
    int e = blockIdx.x * blockDim.x + threadIdx.x;
    if (e >= EE) return;
    int dst = g_is64 ? p32[2 * (EE + e)] : p32[EE + e];
    atomicAdd(&g_deg[dst], 1);
}

// per-scan-block sums (full-chip parallel)
__global__ __launch_bounds__(SBLK) void k_bsum() {
    __shared__ int sh[SBLK];
    int i = blockIdx.x * SBLK + threadIdx.x;
    sh[threadIdx.x] = (i < NN) ? g_deg[i] : 0;
    __syncthreads();
#pragma unroll
    for (int off = SBLK / 2; off > 0; off >>= 1) {
        if (threadIdx.x < off) sh[threadIdx.x] += sh[threadIdx.x + off];
        __syncthreads();
    }
    if (threadIdx.x == 0) g_bsum[blockIdx.x] = sh[0];
}

// offsets: block base = warp-reduce of g_bsum prefix; also writes g_dinv
__global__ __launch_bounds__(SBLK) void k_offsets() {
    __shared__ int sh[SBLK];
    __shared__ int sbase;
    int tid = threadIdx.x;
    if (tid == 0) sbase = 0;
    __syncthreads();
    int v = (tid < blockIdx.x) ? g_bsum[tid] : 0;   // NBLK=196 <= 256
#pragma unroll
    for (int o = 16; o > 0; o >>= 1) v += __shfl_down_sync(0xffffffffu, v, o);
    if ((tid & 31) == 0) atomicAdd(&sbase, v);

    int i = blockIdx.x * SBLK + tid;
    int d = (i < NN) ? g_deg[i] : 0;
    sh[tid] = d;
    __syncthreads();
#pragma unroll
    for (int off = 1; off < SBLK; off <<= 1) {
        int w = (tid >= off) ? sh[tid - off] : 0;
        __syncthreads();
        sh[tid] += w;
        __syncthreads();
    }
    if (i < NN) {
        int o = sbase + sh[tid] - d;   // exclusive
        g_off[i] = o;
        g_cur[i] = o;
        g_dinv[i] = rsqrtf((float)(d + 1));
    }
}

__global__ __launch_bounds__(256) void k_fill(const int* __restrict__ p32) {
    int e = blockIdx.x * blockDim.x + threadIdx.x;
    if (e >= EE) return;
    int src, dst;
    if (g_is64) {
        src = p32[2 * e];
        dst = p32[2 * (EE + e)];
    } else {
        src = p32[e];
        dst = p32[EE + e];
    }
    int pos = atomicAdd(&g_cur[dst], 1);
    g_csr[pos] = src;
}

// ---------------- GEMM: g_hs = f(A) @ W  (r8-proven shape; dinv in k_agg) --------
// 128x128 tile/block (391 blocks), 256 threads, 8x8 micro-tile, f32x2 FMAs.
// A padded to 130 -> LDS.64 A loads; W rows via ulonglong2 -> LDS.128.
#define TM 128
#define KCH 64
#define APAD 130
#define GEMM_SMEM (((KCH * FF) + (FF * APAD) + 2 * FF) * 4)

__global__ __launch_bounds__(256, 2) void k_gemm(const float* __restrict__ A,
                                                 const float* __restrict__ W,
                                                 const float* __restrict__ stats,
                                                 const float* __restrict__ gam,
                                                 const float* __restrict__ bet,
                                                 const float* __restrict__ aw) {
    extern __shared__ float sm[];
    float* Ws  = sm;                              // [KCH][128] chunk
    float* As  = sm + KCH * FF;                   // [k*APAD + r], full K
    float* ssc = sm + KCH * FF + FF * APAD;       // [128] BN scale
    float* sof = ssc + FF;                        // [128] BN offset
    int tid = threadIdx.x;
    int row0 = blockIdx.x * TM;
    bool fuse = (stats != nullptr);
    float a1 = 0.f;

    if (fuse) {
        if (tid < FF) {
            const float invN = 1.f / (float)NN;
            float mu  = stats[tid] * invN;
            float var = stats[FF + tid] * invN - mu * mu;
            float inv = rsqrtf(var + 1e-5f);
            float sc  = gam[tid] * inv;
            ssc[tid] = sc;
            sof[tid] = bet[tid] - mu * sc;
        }
        a1 = __ldg(&aw[0]);
        __syncthreads();
    }

    if (fuse) {
        for (int i = tid; i < TM * FF; i += 256) {
            int r = i >> 7, k = i & 127;
            int gr = row0 + r;
            float v = 0.f;
            if (gr < NN) {
                float t = A[gr * FF + k] * ssc[k] + sof[k];
                v = (t >= 0.f) ? t : a1 * t;
            }
            As[k * APAD + r] = v;
        }
    } else {
        for (int i = tid; i < TM * FF; i += 256) {
            int r = i >> 7, k = i & 127;
            int gr = row0 + r;
            As[k * APAD + r] = (gr < NN) ? A[gr * FF + k] : 0.f;
        }
    }

    int tx = tid & 15, ty = tid >> 4;   // 16 x 16
    int i0 = ty * 8, j0 = tx * 8;

    unsigned long long acc[8][4];
#pragma unroll
    for (int r = 0; r < 8; r++)
#pragma unroll
        for (int c = 0; c < 4; c++) acc[r][c] = 0ull;

    for (int kc = 0; kc < FF / KCH; kc++) {
        __syncthreads();   // Ws free to overwrite (covers As staging on kc=0)
        {
            const float4* Wg = (const float4*)(W + kc * KCH * FF);
            float4* Wv = (float4*)Ws;
            for (int i = tid; i < KCH * FF / 4; i += 256) Wv[i] = Wg[i];
        }
        __syncthreads();
#pragma unroll 2
        for (int k = 0; k < KCH; k++) {
            const float* wrow = Ws + k * FF + j0;
            ulonglong2 wA = *(const ulonglong2*)(wrow);      // LDS.128
            ulonglong2 wB = *(const ulonglong2*)(wrow + 4);  // LDS.128
            const float* ar = As + (kc * KCH + k) * APAD + i0;
            float2 p0 = *(const float2*)(ar + 0);            // LDS.64
            float2 p1 = *(const float2*)(ar + 2);
            float2 p2 = *(const float2*)(ar + 4);
            float2 p3 = *(const float2*)(ar + 6);
            float av[8] = {p0.x, p0.y, p1.x, p1.y, p2.x, p2.y, p3.x, p3.y};
#pragma unroll
            for (int r = 0; r < 8; r++) {
                unsigned long long aa = pack2(av[r]);
                acc[r][0] = fma2(aa, wA.x, acc[r][0]);
                acc[r][1] = fma2(aa, wA.y, acc[r][1]);
                acc[r][2] = fma2(aa, wB.x, acc[r][2]);
                acc[r][3] = fma2(aa, wB.y, acc[r][3]);
            }
        }
    }

#pragma unroll
    for (int r = 0; r < 8; r++) {
        int gr = row0 + i0 + r;
        if (gr < NN) {
            float2 p;
            float4 o0, o1;
            p = unpack2(acc[r][0]); o0.x = p.x; o0.y = p.y;
            p = unpack2(acc[r][1]); o0.z = p.x; o0.w = p.y;
            p = unpack2(acc[r][2]); o1.x = p.x; o1.y = p.y;
            p = unpack2(acc[r][3]); o1.z = p.x; o1.w = p.y;
            float4* dst = (float4*)(g_hs + gr * FF + j0);
            dst[0] = o0;
            dst[1] = o1;
        }
    }
}

// ---------------- aggregation (applies ALL dinv scaling; 4-way unrolled) ----------
// agg[dst] = dinv[dst] * ( h[dst]*dinv[dst] + sum_src h[src]*dinv[src] )
__global__ __launch_bounds__(256) void k_agg() {
    int tid = threadIdx.x;
    int lane = tid & 31;
    int gw = (blockIdx.x * 256 + tid) >> 5;   // node id (1 warp per node)
    const float4* b = (const float4*)g_hs;
    float dself = __ldg(&g_dinv[gw]);
    float4 a0 = b[gw * 32 + lane];
    a0.x *= dself; a0.y *= dself; a0.z *= dself; a0.w *= dself;
    float4 a1 = {0.f, 0.f, 0.f, 0.f};
    float4 a2 = {0.f, 0.f, 0.f, 0.f};
    float4 a3 = {0.f, 0.f, 0.f, 0.f};
    int s = g_off[gw];
    int n = g_deg[gw];
    int e = s, end4 = s + (n & ~3);
    for (; e < end4; e += 4) {
        int s0 = __ldg(&g_csr[e + 0]);
        int s1 = __ldg(&g_csr[e + 1]);
        int s2 = __ldg(&g_csr[e + 2]);
        int s3 = __ldg(&g_csr[e + 3]);
        float d0 = __ldg(&g_dinv[s0]);
        float d1 = __ldg(&g_dinv[s1]);
        float d2 = __ldg(&g_dinv[s2]);
        float d3 = __ldg(&g_dinv[s3]);
        float4 v0 = b[s0 * 32 + lane];
        float4 v1 = b[s1 * 32 + lane];
        float4 v2 = b[s2 * 32 + lane];
        float4 v3 = b[s3 * 32 + lane];
        a0.x = fmaf(v0.x, d0, a0.x); a0.y = fmaf(v0.y, d0, a0.y);
        a0.z = fmaf(v0.z, d0, a0.z); a0.w = fmaf(v0.w, d0, a0.w);
        a1.x = fmaf(v1.x, d1, a1.x); a1.y = fmaf(v1.y, d1, a1.y);
        a1.z = fmaf(v1.z, d1, a1.z); a1.w = fmaf(v1.w, d1, a1.w);
        a2.x = fmaf(v2.x, d2, a2.x); a2.y = fmaf(v2.y, d2, a2.y);
        a2.z = fmaf(v2.z, d2, a2.z); a2.w = fmaf(v2.w, d2, a2.w);
        a3.x = fmaf(v3.x, d3, a3.x); a3.y = fmaf(v3.y, d3, a3.y);
        a3.z = fmaf(v3.z, d3, a3.z); a3.w = fmaf(v3.w, d3, a3.w);
    }
    for (; e < s + n; e++) {
        int s0 = __ldg(&g_csr[e]);
        float d0 = __ldg(&g_dinv[s0]);
        float4 v0 = b[s0 * 32 + lane];
        a0.x = fmaf(v0.x, d0, a0.x); a0.y = fmaf(v0.y, d0, a0.y);
        a0.z = fmaf(v0.z, d0, a0.z); a0.w = fmaf(v0.w, d0, a0.w);
    }
    a0.x += a1.x + a2.x + a3.x;
    a0.y += a1.y + a2.y + a3.y;
    a0.z += a1.z + a2.z + a3.z;
    a0.w += a1.w + a2.w + a3.w;
    a0.x *= dself; a0.y *= dself; a0.z *= dself; a0.w *= dself;
    ((float4*)g_agg)[gw * 32 + lane] = a0;
}

// column sums / sumsq (proven; 102K atomics over 256 addrs)
__global__ __launch_bounds__(128) void k_reduce(float* __restrict__ stats) {
    int col = threadIdx.x;  // blockDim = 128
    int r0 = blockIdx.x * 125;
    int r1 = min(r0 + 125, NN);
    float s = 0.f, q = 0.f;
    for (int r = r0; r < r1; r++) {
        float v = g_agg[r * FF + col];
        s += v;
        q += v * v;
    }
    atomicAdd(&stats[col], s);
    atomicAdd(&stats[FF + col], q);
}

// BatchNorm (biased var) + PReLU for the final layer
__global__ __launch_bounds__(256) void k_norm(const float* __restrict__ stats,
                                              const float* __restrict__ gam,
                                              const float* __restrict__ bet,
                                              const float* __restrict__ aw,
                                              float* __restrict__ out) {
    int idx = blockIdx.x * blockDim.x + threadIdx.x;
    int c = (idx & 31) * 4;
    float4 v = ((const float4*)g_agg)[idx];
    float a = __ldg(&aw[0]);
    float vv[4] = {v.x, v.y, v.z, v.w};
    float o[4];
    const float invN = 1.f / (float)NN;
#pragma unroll
    for (int j = 0; j < 4; j++) {
        float mu  = stats[c + j] * invN;
        float var = stats[FF + c + j] * invN - mu * mu;
        float inv = rsqrtf(var + 1e-5f);
        float sc  = gam[c + j] * inv;
        float of  = bet[c + j] - mu * sc;
        float t = vv[j] * sc + of;
        o[j] = (t >= 0.f) ? t : a * t;
    }
    float4 r = {o[0], o[1], o[2], o[3]};
    ((float4*)out)[idx] = r;
}

// ---------------- eager load + cached device ptrs + fork stream (static init) ----
namespace {
float* p_agg = nullptr;
float* p_st1 = nullptr;
float* p_st2 = nullptr;
cudaStream_t s_fork = nullptr;
cudaEvent_t  ev_in = nullptr, ev_gemm = nullptr;
struct HxEagerLoad {
    HxEagerLoad() {
        void* p = nullptr;
        cudaGetSymbolAddress(&p, g_hs);    // triggers full module load
        cudaGetSymbolAddress(&p, g_csr);
        cudaGetSymbolAddress((void**)&p_agg, g_agg);
        cudaGetSymbolAddress((void**)&p_st1, g_stats1);
        cudaGetSymbolAddress((void**)&p_st2, g_stats2);
        cudaFuncSetAttribute(k_gemm, cudaFuncAttributeMaxDynamicSharedMemorySize,
                             GEMM_SMEM);
        cudaStreamCreateWithFlags(&s_fork, cudaStreamNonBlocking);
        cudaEventCreateWithFlags(&ev_in, cudaEventDisableTiming);
        cudaEventCreateWithFlags(&ev_gemm, cudaEventDisableTiming);
    }
};
HxEagerLoad hx_eager_load_;
}  // namespace

// ---------------- launch ----------------------------------------------------------
extern "C" void kernel_launch(void* const* d_in, const int* in_sizes, int n_in,
                              void* d_out, int out_size) {
    const float* x   = (const float*)d_in[0];
    const int*   ei  = (const int*)d_in[1];
    const float* W1  = (const float*)d_in[2];
    const float* gm1 = (const float*)d_in[4];
    const float* be1 = (const float*)d_in[5];
    const float* a1  = (const float*)d_in[6];
    const float* W2  = (const float*)d_in[7];
    const float* gm2 = (const float*)d_in[9];
    const float* be2 = (const float*)d_in[10];
    const float* a2  = (const float*)d_in[11];
    float* out = (float*)d_out;

    const int gemm_blocks = (NN + TM - 1) / TM;   // 391
    const int agg_blocks  = (NN * 32) / 256;      // 6250 exact
    const int red_blocks  = (NN + 124) / 125;     // 400

    // fork point: GEMM1 depends only on inputs, not the CSR build
    cudaEventRecord(ev_in, 0);
    cudaStreamWaitEvent(s_fork, ev_in, 0);

    // GEMM1 concurrent on forked stream
    k_gemm<<<gemm_blocks, 256, GEMM_SMEM, s_fork>>>(
        x, W1, nullptr, nullptr, nullptr, nullptr);
    cudaEventRecord(ev_gemm, s_fork);

    // CSR build chain (default stream)
    k_init<<<NBLK, SBLK>>>((const unsigned int*)ei);
    k_count<<<(EE + 255) / 256, 256>>>(ei);
    k_bsum<<<NBLK, SBLK>>>();
    k_offsets<<<NBLK, SBLK>>>();
    k_fill<<<(EE + 255) / 256, 256>>>(ei);

    cudaStreamWaitEvent(0, ev_gemm, 0);

    // join: layer-1 aggregation onward (default stream)
    k_agg<<<agg_blocks, 256>>>();
    k_reduce<<<red_blocks, 128>>>(p_st1);
    k_gemm<<<gemm_blocks, 256, GEMM_SMEM>>>(p_agg, W2,   // BN1+PReLU fused
                                            p_st1, gm1, be1, a1);
    k_agg<<<agg_blocks, 256>>>();
    k_reduce<<<red_blocks, 128>>>(p_st2);
    k_norm<<<agg_blocks, 256>>>(p_st2, gm2, be2, a2, out);
}

// round 11
// speedup vs baseline: 1.1374x; 1.0556x over previous
#include <cuda_runtime.h>
#include <cuda_fp16.h>

#define NN 50000
#define EE 800000
#define FF 128
#define SBLK 256
#define NBLK ((NN + SBLK - 1) / SBLK)   // 196

// ---------------- scratch (device globals; sanctioned scratch mechanism) ---------
__device__ int    g_is64;
__device__ int    g_deg[NN];
__device__ int    g_off[NN];
__device__ int    g_cur[NN];
__device__ float  g_dinv[NN];
__device__ int    g_csr[EE];
__device__ __half g_hs[NN * FF];     // fp16 GEMM output (halves gather traffic)
__device__ float  g_agg[NN * FF];
__device__ float  g_stats1[2 * FF];
__device__ float  g_stats2[2 * FF];
__device__ int    g_bsum[NBLK];

// ---------------- f32x2 helpers ---------------------------------------------------
__device__ __forceinline__ unsigned long long fma2(unsigned long long a,
                                                   unsigned long long b,
                                                   unsigned long long c) {
    unsigned long long d;
    asm("fma.rn.f32x2 %0, %1, %2, %3;" : "=l"(d) : "l"(a), "l"(b), "l"(c));
    return d;
}
__device__ __forceinline__ unsigned long long pack2(float x) {
    unsigned long long r;
    asm("mov.b64 %0, {%1, %1};" : "=l"(r) : "f"(x));
    return r;
}
__device__ __forceinline__ float2 unpack2(unsigned long long v) {
    float2 f;
    asm("mov.b64 {%0, %1}, %2;" : "=f"(f.x), "=f"(f.y) : "l"(v));
    return f;
}
__device__ __forceinline__ unsigned h2u(__half2 h) {
    return *reinterpret_cast<unsigned*>(&h);
}
__device__ __forceinline__ float2 u2f2(unsigned u) {
    __half2 h = *reinterpret_cast<__half2*>(&u);
    return __half22float2(h);
}

// ---------------- init: zero deg/stats + dtype detect ----------------------------
__global__ __launch_bounds__(SBLK) void k_init(const unsigned int* __restrict__ p) {
    int gi = blockIdx.x * SBLK + threadIdx.x;
    if (gi < NN) g_deg[gi] = 0;
    if (gi < 2 * FF) { g_stats1[gi] = 0.f; g_stats2[gi] = 0.f; }
    if (blockIdx.x == 0) {
        __shared__ int any;
        if (threadIdx.x == 0) any = 0;
        __syncthreads();
        if (p[2 * threadIdx.x + 1] != 0u) atomicOr(&any, 1);
        __syncthreads();
        if (threadIdx.x == 0) g_is64 = !any;
    }
}

// degree count (32-bit low-word loads; node ids < 2^31)
__global__ __launch_bounds__(256) void k_count(const int* __restrict__ p32) {
    int e = blockIdx.x * blockDim.x + threadIdx.x;
    if (e >= EE) return;
    int dst = g_is64 ? p32[2 * (EE + e)] : p32[EE + e];
    atomicAdd(&g_deg[dst], 1);
}

// per-scan-block sums (full-chip parallel)
__global__ __launch_bounds__(SBLK) void k_bsum() {
    __shared__ int sh[SBLK];
    int i = blockIdx.x * SBLK + threadIdx.x;
    sh[threadIdx.x] = (i < NN) ? g_deg[i] : 0;
    __syncthreads();
#pragma unroll
    for (int off = SBLK / 2; off > 0; off >>= 1) {
        if (threadIdx.x < off) sh[threadIdx.x] += sh[threadIdx.x + off];
        __syncthreads();
    }
    if (threadIdx.x == 0) g_bsum[blockIdx.x] = sh[0];
}

// offsets: block base = warp-reduce of g_bsum prefix; also writes g_dinv
__global__ __launch_bounds__(SBLK) void k_offsets() {
    __shared__ int sh[SBLK];
    __shared__ int sbase;
    int tid = threadIdx.x;
    if (tid == 0) sbase = 0;
    __syncthreads();
    int v = (tid < blockIdx.x) ? g_bsum[tid] : 0;   // NBLK=196 <= 256
#pragma unroll
    for (int o = 16; o > 0; o >>= 1) v += __shfl_down_sync(0xffffffffu, v, o);
    if ((tid & 31) == 0) atomicAdd(&sbase, v);

    int i = blockIdx.x * SBLK + tid;
    int d = (i < NN) ? g_deg[i] : 0;
    sh[tid] = d;
    __syncthreads();
#pragma unroll
    for (int off = 1; off < SBLK; off <<= 1) {
        int w = (tid >= off) ? sh[tid - off] : 0;
        __syncthreads();
        sh[tid] += w;
        __syncthreads();
    }
    if (i < NN) {
        int o = sbase + sh[tid] - d;   // exclusive
        g_off[i] = o;
        g_cur[i] = o;
        g_dinv[i] = rsqrtf((float)(d + 1));
    }
}

__global__ __launch_bounds__(256) void k_fill(const int* __restrict__ p32) {
    int e = blockIdx.x * blockDim.x + threadIdx.x;
    if (e >= EE) return;
    int src, dst;
    if (g_is64) {
        src = p32[2 * e];
        dst = p32[2 * (EE + e)];
    } else {
        src = p32[e];
        dst = p32[EE + e];
    }
    int pos = atomicAdd(&g_cur[dst], 1);
    g_csr[pos] = src;
}

// ---------------- GEMM: g_hs = f(A) @ W  (fp16 output; dinv in k_agg) ------------
// 128x128 tile/block (391 blocks), 256 threads, 8x8 micro-tile, f32x2 FMAs.
#define TM 128
#define KCH 64
#define APAD 130
#define GEMM_SMEM (((KCH * FF) + (FF * APAD) + 2 * FF) * 4)

__global__ __launch_bounds__(256, 2) void k_gemm(const float* __restrict__ A,
                                                 const float* __restrict__ W,
                                                 const float* __restrict__ stats,
                                                 const float* __restrict__ gam,
                                                 const float* __restrict__ bet,
                                                 const float* __restrict__ aw) {
    extern __shared__ float sm[];
    float* Ws  = sm;                              // [KCH][128] chunk
    float* As  = sm + KCH * FF;                   // [k*APAD + r], full K
    float* ssc = sm + KCH * FF + FF * APAD;       // [128] BN scale
    float* sof = ssc + FF;                        // [128] BN offset
    int tid = threadIdx.x;
    int row0 = blockIdx.x * TM;
    bool fuse = (stats != nullptr);
    float a1 = 0.f;

    if (fuse) {
        if (tid < FF) {
            const float invN = 1.f / (float)NN;
            float mu  = stats[tid] * invN;
            float var = stats[FF + tid] * invN - mu * mu;
            float inv = rsqrtf(var + 1e-5f);
            float sc  = gam[tid] * inv;
            ssc[tid] = sc;
            sof[tid] = bet[tid] - mu * sc;
        }
        a1 = __ldg(&aw[0]);
        __syncthreads();
    }

    if (fuse) {
        for (int i = tid; i < TM * FF; i += 256) {
            int r = i >> 7, k = i & 127;
            int gr = row0 + r;
            float v = 0.f;
            if (gr < NN) {
                float t = A[gr * FF + k] * ssc[k] + sof[k];
                v = (t >= 0.f) ? t : a1 * t;
            }
            As[k * APAD + r] = v;
        }
    } else {
        for (int i = tid; i < TM * FF; i += 256) {
            int r = i >> 7, k = i & 127;
            int gr = row0 + r;
            As[k * APAD + r] = (gr < NN) ? A[gr * FF + k] : 0.f;
        }
    }

    int tx = tid & 15, ty = tid >> 4;   // 16 x 16
    int i0 = ty * 8, j0 = tx * 8;

    unsigned long long acc[8][4];
#pragma unroll
    for (int r = 0; r < 8; r++)
#pragma unroll
        for (int c = 0; c < 4; c++) acc[r][c] = 0ull;

    for (int kc = 0; kc < FF / KCH; kc++) {
        __syncthreads();   // Ws free to overwrite (covers As staging on kc=0)
        {
            const float4* Wg = (const float4*)(W + kc * KCH * FF);
            float4* Wv = (float4*)Ws;
            for (int i = tid; i < KCH * FF / 4; i += 256) Wv[i] = Wg[i];
        }
        __syncthreads();
#pragma unroll 2
        for (int k = 0; k < KCH; k++) {
            const float* wrow = Ws + k * FF + j0;
            ulonglong2 wA = *(const ulonglong2*)(wrow);      // LDS.128
            ulonglong2 wB = *(const ulonglong2*)(wrow + 4);  // LDS.128
            const float* ar = As + (kc * KCH + k) * APAD + i0;
            float2 p0 = *(const float2*)(ar + 0);            // LDS.64
            float2 p1 = *(const float2*)(ar + 2);
            float2 p2 = *(const float2*)(ar + 4);
            float2 p3 = *(const float2*)(ar + 6);
            float av[8] = {p0.x, p0.y, p1.x, p1.y, p2.x, p2.y, p3.x, p3.y};
#pragma unroll
            for (int r = 0; r < 8; r++) {
                unsigned long long aa = pack2(av[r]);
                acc[r][0] = fma2(aa, wA.x, acc[r][0]);
                acc[r][1] = fma2(aa, wA.y, acc[r][1]);
                acc[r][2] = fma2(aa, wB.x, acc[r][2]);
                acc[r][3] = fma2(aa, wB.y, acc[r][3]);
            }
        }
    }

#pragma unroll
    for (int r = 0; r < 8; r++) {
        int gr = row0 + i0 + r;
        if (gr < NN) {
            float2 p0 = unpack2(acc[r][0]);
            float2 p1 = unpack2(acc[r][1]);
            float2 p2 = unpack2(acc[r][2]);
            float2 p3 = unpack2(acc[r][3]);
            uint4 u;
            u.x = h2u(__float22half2_rn(p0));
            u.y = h2u(__float22half2_rn(p1));
            u.z = h2u(__float22half2_rn(p2));
            u.w = h2u(__float22half2_rn(p3));
            *(uint4*)(g_hs + gr * FF + j0) = u;   // 8 halfs, STG.128
        }
    }
}

// ---------------- aggregation (fp16 gathers; fp32 accumulate; 4-way unrolled) -----
// agg[dst] = dinv[dst] * ( h[dst]*dinv[dst] + sum_src h[src]*dinv[src] )
__global__ __launch_bounds__(256) void k_agg() {
    int tid = threadIdx.x;
    int lane = tid & 31;
    int gw = (blockIdx.x * 256 + tid) >> 5;   // node id (1 warp per node)
    const uint2* b = (const uint2*)g_hs;      // row = 32 uint2 (4 halfs each)
    float dself = __ldg(&g_dinv[gw]);

    uint2 us = __ldg(&b[gw * 32 + lane]);
    float2 sf0 = u2f2(us.x), sf1 = u2f2(us.y);
    float4 a0 = {sf0.x * dself, sf0.y * dself, sf1.x * dself, sf1.y * dself};
    float4 a1 = {0.f, 0.f, 0.f, 0.f};
    float4 a2 = {0.f, 0.f, 0.f, 0.f};
    float4 a3 = {0.f, 0.f, 0.f, 0.f};

    int s = g_off[gw];
    int n = g_deg[gw];
    int e = s, end4 = s + (n & ~3);
    for (; e < end4; e += 4) {
        int s0 = __ldg(&g_csr[e + 0]);
        int s1 = __ldg(&g_csr[e + 1]);
        int s2 = __ldg(&g_csr[e + 2]);
        int s3 = __ldg(&g_csr[e + 3]);
        float d0 = __ldg(&g_dinv[s0]);
        float d1 = __ldg(&g_dinv[s1]);
        float d2 = __ldg(&g_dinv[s2]);
        float d3 = __ldg(&g_dinv[s3]);
        uint2 u0 = __ldg(&b[s0 * 32 + lane]);
        uint2 u1 = __ldg(&b[s1 * 32 + lane]);
        uint2 u2 = __ldg(&b[s2 * 32 + lane]);
        uint2 u3 = __ldg(&b[s3 * 32 + lane]);
        float2 f0a = u2f2(u0.x), f0b = u2f2(u0.y);
        float2 f1a = u2f2(u1.x), f1b = u2f2(u1.y);
        float2 f2a = u2f2(u2.x), f2b = u2f2(u2.y);
        float2 f3a = u2f2(u3.x), f3b = u2f2(u3.y);
        a0.x = fmaf(f0a.x, d0, a0.x); a0.y = fmaf(f0a.y, d0, a0.y);
        a0.z = fmaf(f0b.x, d0, a0.z); a0.w = fmaf(f0b.y, d0, a0.w);
        a1.x = fmaf(f1a.x, d1, a1.x); a1.y = fmaf(f1a.y, d1, a1.y);
        a1.z = fmaf(f1b.x, d1, a1.z); a1.w = fmaf(f1b.y, d1, a1.w);
        a2.x = fmaf(f2a.x, d2, a2.x); a2.y = fmaf(f2a.y, d2, a2.y);
        a2.z = fmaf(f2b.x, d2, a2.z); a2.w = fmaf(f2b.y, d2, a2.w);
        a3.x = fmaf(f3a.x, d3, a3.x); a3.y = fmaf(f3a.y, d3, a3.y);
        a3.z = fmaf(f3b.x, d3, a3.w == a3.w ? a3.z : a3.z); a3.w = fmaf(f3b.y, d3, a3.w);
    }
    for (; e < s + n; e++) {
        int s0 = __ldg(&g_csr[e]);
        float d0 = __ldg(&g_dinv[s0]);
        uint2 u0 = __ldg(&b[s0 * 32 + lane]);
        float2 f0a = u2f2(u0.x), f0b = u2f2(u0.y);
        a0.x = fmaf(f0a.x, d0, a0.x); a0.y = fmaf(f0a.y, d0, a0.y);
        a0.z = fmaf(f0b.x, d0, a0.z); a0.w = fmaf(f0b.y, d0, a0.w);
    }
    a0.x += a1.x + a2.x + a3.x;
    a0.y += a1.y + a2.y + a3.y;
    a0.z += a1.z + a2.z + a3.z;
    a0.w += a1.w + a2.w + a3.w;
    a0.x *= dself; a0.y *= dself; a0.z *= dself; a0.w *= dself;
    ((float4*)g_agg)[gw * 32 + lane] = a0;
}

// column sums / sumsq (proven; 102K atomics over 256 addrs)
__global__ __launch_bounds__(128) void k_reduce(float* __restrict__ stats) {
    int col = threadIdx.x;  // blockDim = 128
    int r0 = blockIdx.x * 125;
    int r1 = min(r0 + 125, NN);
    float s = 0.f, q = 0.f;
    for (int r = r0; r < r1; r++) {
        float v = g_agg[r * FF + col];
        s += v;
        q += v * v;
    }
    atomicAdd(&stats[col], s);
    atomicAdd(&stats[FF + col], q);
}

// BatchNorm (biased var) + PReLU for the final layer
__global__ __launch_bounds__(256) void k_norm(const float* __restrict__ stats,
                                              const float* __restrict__ gam,
                                              const float* __restrict__ bet,
                                              const float* __restrict__ aw,
                                              float* __restrict__ out) {
    int idx = blockIdx.x * blockDim.x + threadIdx.x;
    int c = (idx & 31) * 4;
    float4 v = ((const float4*)g_agg)[idx];
    float a = __ldg(&aw[0]);
    float vv[4] = {v.x, v.y, v.z, v.w};
    float o[4];
    const float invN = 1.f / (float)NN;
#pragma unroll
    for (int j = 0; j < 4; j++) {
        float mu  = stats[c + j] * invN;
        float var = stats[FF + c + j] * invN - mu * mu;
        float inv = rsqrtf(var + 1e-5f);
        float sc  = gam[c + j] * inv;
        float of  = bet[c + j] - mu * sc;
        float t = vv[j] * sc + of;
        o[j] = (t >= 0.f) ? t : a * t;
    }
    float4 r = {o[0], o[1], o[2], o[3]};
    ((float4*)out)[idx] = r;
}

// ---------------- eager load + cached device ptrs + fork stream (static init) ----
namespace {
float* p_agg = nullptr;
float* p_st1 = nullptr;
float* p_st2 = nullptr;
cudaStream_t s_fork = nullptr;
cudaEvent_t  ev_in = nullptr, ev_gemm = nullptr;
struct HxEagerLoad {
    HxEagerLoad() {
        void* p = nullptr;
        cudaGetSymbolAddress(&p, g_hs);    // triggers full module load
        cudaGetSymbolAddress(&p, g_csr);
        cudaGetSymbolAddress((void**)&p_agg, g_agg);
        cudaGetSymbolAddress((void**)&p_st1, g_stats1);
        cudaGetSymbolAddress((void**)&p_st2, g_stats2);
        cudaFuncSetAttribute(k_gemm, cudaFuncAttributeMaxDynamicSharedMemorySize,
                             GEMM_SMEM);
        cudaStreamCreateWithFlags(&s_fork, cudaStreamNonBlocking);
        cudaEventCreateWithFlags(&ev_in, cudaEventDisableTiming);
        cudaEventCreateWithFlags(&ev_gemm, cudaEventDisableTiming);
    }
};
HxEagerLoad hx_eager_load_;
}  // namespace

// ---------------- launch ----------------------------------------------------------
extern "C" void kernel_launch(void* const* d_in, const int* in_sizes, int n_in,
                              void* d_out, int out_size) {
    const float* x   = (const float*)d_in[0];
    const int*   ei  = (const int*)d_in[1];
    const float* W1  = (const float*)d_in[2];
    const float* gm1 = (const float*)d_in[4];
    const float* be1 = (const float*)d_in[5];
    const float* a1  = (const float*)d_in[6];
    const float* W2  = (const float*)d_in[7];
    const float* gm2 = (const float*)d_in[9];
    const float* be2 = (const float*)d_in[10];
    const float* a2  = (const float*)d_in[11];
    float* out = (float*)d_out;

    const int gemm_blocks = (NN + TM - 1) / TM;   // 391
    const int agg_blocks  = (NN * 32) / 256;      // 6250 exact
    const int red_blocks  = (NN + 124) / 125;     // 400

    // fork point: GEMM1 depends only on inputs, not the CSR build
    cudaEventRecord(ev_in, 0);
    cudaStreamWaitEvent(s_fork, ev_in, 0);

    // GEMM1 concurrent on forked stream
    k_gemm<<<gemm_blocks, 256, GEMM_SMEM, s_fork>>>(
        x, W1, nullptr, nullptr, nullptr, nullptr);
    cudaEventRecord(ev_gemm, s_fork);

    // CSR build chain (default stream)
    k_init<<<NBLK, SBLK>>>((const unsigned int*)ei);
    k_count<<<(EE + 255) / 256, 256>>>(ei);
    k_bsum<<<NBLK, SBLK>>>();
    k_offsets<<<NBLK, SBLK>>>();
    k_fill<<<(EE + 255) / 256, 256>>>(ei);

    cudaStreamWaitEvent(0, ev_gemm, 0);

    // join: layer-1 aggregation onward (default stream)
    k_agg<<<agg_blocks, 256>>>();
    k_reduce<<<red_blocks, 128>>>(p_st1);
    k_gemm<<<gemm_blocks, 256, GEMM_SMEM>>>(p_agg, W2,   // BN1+PReLU fused
                                            p_st1, gm1, be1, a1);
    k_agg<<<agg_blocks, 256>>>();
    k_reduce<<<red_blocks, 128>>>(p_st2);
    k_norm<<<agg_blocks, 256>>>(p_st2, gm2, be2, a2, out);
}

// round 12
// speedup vs baseline: 1.2415x; 1.0916x over previous
#include <cuda_runtime.h>
#include <cuda_fp16.h>
#include <mma.h>

using namespace nvcuda;

#define NN 50000
#define EE 800000
#define FF 128
#define SBLK 256
#define NBLK ((NN + SBLK - 1) / SBLK)   // 196

// ---------------- scratch (device globals; sanctioned scratch mechanism) ---------
__device__ int    g_is64;
__device__ int    g_deg[NN];
__device__ int    g_off[NN];
__device__ int    g_cur[NN];
__device__ float  g_dinv[NN];
__device__ int    g_csr[EE];
__device__ __half g_hs[NN * FF];     // fp16 GEMM output (halves gather traffic)
__device__ float  g_agg[NN * FF];
__device__ float  g_stats1[2 * FF];
__device__ float  g_stats2[2 * FF];
__device__ int    g_bsum[NBLK];

__device__ __forceinline__ unsigned h2u(__half2 h) {
    return *reinterpret_cast<unsigned*>(&h);
}
__device__ __forceinline__ float2 u2f2(unsigned u) {
    __half2 h = *reinterpret_cast<__half2*>(&u);
    return __half22float2(h);
}

// ---------------- init: zero deg/stats + dtype detect ----------------------------
__global__ __launch_bounds__(SBLK) void k_init(const unsigned int* __restrict__ p) {
    int gi = blockIdx.x * SBLK + threadIdx.x;
    if (gi < NN) g_deg[gi] = 0;
    if (gi < 2 * FF) { g_stats1[gi] = 0.f; g_stats2[gi] = 0.f; }
    if (blockIdx.x == 0) {
        __shared__ int any;
        if (threadIdx.x == 0) any = 0;
        __syncthreads();
        if (p[2 * threadIdx.x + 1] != 0u) atomicOr(&any, 1);
        __syncthreads();
        if (threadIdx.x == 0) g_is64 = !any;
    }
}

// degree count (32-bit low-word loads; node ids < 2^31)
__global__ __launch_bounds__(256) void k_count(const int* __restrict__ p32) {
    int e = blockIdx.x * blockDim.x + threadIdx.x;
    if (e >= EE) return;
    int dst = g_is64 ? p32[2 * (EE + e)] : p32[EE + e];
    atomicAdd(&g_deg[dst], 1);
}

// per-scan-block sums (full-chip parallel)
__global__ __launch_bounds__(SBLK) void k_bsum() {
    __shared__ int sh[SBLK];
    int i = blockIdx.x * SBLK + threadIdx.x;
    sh[threadIdx.x] = (i < NN) ? g_deg[i] : 0;
    __syncthreads();
#pragma unroll
    for (int off = SBLK / 2; off > 0; off >>= 1) {
        if (threadIdx.x < off) sh[threadIdx.x] += sh[threadIdx.x + off];
        __syncthreads();
    }
    if (threadIdx.x == 0) g_bsum[blockIdx.x] = sh[0];
}

// offsets: block base = warp-reduce of g_bsum prefix; also writes g_dinv
__global__ __launch_bounds__(SBLK) void k_offsets() {
    __shared__ int sh[SBLK];
    __shared__ int sbase;
    int tid = threadIdx.x;
    if (tid == 0) sbase = 0;
    __syncthreads();
    int v = (tid < blockIdx.x) ? g_bsum[tid] : 0;   // NBLK=196 <= 256
#pragma unroll
    for (int o = 16; o > 0; o >>= 1) v += __shfl_down_sync(0xffffffffu, v, o);
    if ((tid & 31) == 0) atomicAdd(&sbase, v);

    int i = blockIdx.x * SBLK + tid;
    int d = (i < NN) ? g_deg[i] : 0;
    sh[tid] = d;
    __syncthreads();
#pragma unroll
    for (int off = 1; off < SBLK; off <<= 1) {
        int w = (tid >= off) ? sh[tid - off] : 0;
        __syncthreads();
        sh[tid] += w;
        __syncthreads();
    }
    if (i < NN) {
        int o = sbase + sh[tid] - d;   // exclusive
        g_off[i] = o;
        g_cur[i] = o;
        g_dinv[i] = rsqrtf((float)(d + 1));
    }
}

__global__ __launch_bounds__(256) void k_fill(const int* __restrict__ p32) {
    int e = blockIdx.x * blockDim.x + threadIdx.x;
    if (e >= EE) return;
    int src, dst;
    if (g_is64) {
        src = p32[2 * e];
        dst = p32[2 * (EE + e)];
    } else {
        src = p32[e];
        dst = p32[EE + e];
    }
    int pos = atomicAdd(&g_cur[dst], 1);
    g_csr[pos] = src;
}

// ---------------- GEMM (tensor cores): g_hs = fp16( f(A) @ W ) -------------------
// 128x128 tile/block (391 blocks), 256 threads = 8 warps.
// W (fp16) and A (fp16, BN1+PReLU fused on convert) staged in smem; wmma
// m16n16k16 HMMA, fp32 accum; epilogue bounces C via smem -> fp16 g_hs.
#define TM 128
#define LDA 136            // half elements (mult of 8 for wmma)
#define LDC 132            // float elements (mult of 4 for wmma store)
#define HS_BYTES (FF * LDA * 2)           // 34816 per operand
#define GEMM_SMEM (2 * HS_BYTES + 2 * FF * 4)   // Wh + Ah + ssc + sof = 70656

__global__ __launch_bounds__(256, 2) void k_gemm(const float* __restrict__ A,
                                                 const float* __restrict__ W,
                                                 const float* __restrict__ stats,
                                                 const float* __restrict__ gam,
                                                 const float* __restrict__ bet,
                                                 const float* __restrict__ aw) {
    extern __shared__ char smraw[];
    __half* Wh = (__half*)smraw;                    // [128][LDA]
    __half* Ah = (__half*)(smraw + HS_BYTES);       // [128][LDA]
    float*  ssc = (float*)(smraw + 2 * HS_BYTES);   // [128] BN scale
    float*  sof = ssc + FF;                         // [128] BN offset
    float*  Cf = (float*)smraw;                     // epilogue reuse [128][LDC]

    int tid = threadIdx.x;
    int wid = tid >> 5;
    int row0 = blockIdx.x * TM;
    bool fuse = (stats != nullptr);
    float a1 = 0.f;

    if (fuse) {
        if (tid < FF) {
            const float invN = 1.f / (float)NN;
            float mu  = stats[tid] * invN;
            float var = stats[FF + tid] * invN - mu * mu;
            float inv = rsqrtf(var + 1e-5f);
            float sc  = gam[tid] * inv;
            ssc[tid] = sc;
            sof[tid] = bet[tid] - mu * sc;
        }
        a1 = __ldg(&aw[0]);
        __syncthreads();
    }

    // stage W -> fp16 smem
    for (int i = tid; i < FF * FF; i += 256) {
        int r = i >> 7, c = i & 127;
        Wh[r * LDA + c] = __float2half(W[i]);
    }
    // stage A -> fp16 smem (optionally BN1+PReLU fused)
    if (fuse) {
        for (int i = tid; i < TM * FF; i += 256) {
            int r = i >> 7, k = i & 127;
            int gr = row0 + r;
            float v = 0.f;
            if (gr < NN) {
                float t = A[gr * FF + k] * ssc[k] + sof[k];
                v = (t >= 0.f) ? t : a1 * t;
            }
            Ah[r * LDA + k] = __float2half(v);
        }
    } else {
        for (int i = tid; i < TM * FF; i += 256) {
            int r = i >> 7, k = i & 127;
            int gr = row0 + r;
            Ah[r * LDA + k] = __float2half((gr < NN) ? A[gr * FF + k] : 0.f);
        }
    }
    __syncthreads();

    // each warp computes rows [wid*16, wid*16+16) x all 128 cols
    wmma::fragment<wmma::accumulator, 16, 16, 16, float> acc[8];
#pragma unroll
    for (int j = 0; j < 8; j++) wmma::fill_fragment(acc[j], 0.f);

#pragma unroll
    for (int k0 = 0; k0 < 8; k0++) {
        wmma::fragment<wmma::matrix_a, 16, 16, 16, __half, wmma::row_major> af;
        wmma::load_matrix_sync(af, Ah + (wid * 16) * LDA + k0 * 16, LDA);
#pragma unroll
        for (int j = 0; j < 8; j++) {
            wmma::fragment<wmma::matrix_b, 16, 16, 16, __half, wmma::row_major> bf;
            wmma::load_matrix_sync(bf, Wh + (k0 * 16) * LDA + j * 16, LDA);
            wmma::mma_sync(acc[j], af, bf, acc[j]);
        }
    }
    __syncthreads();   // all fragment loads done; smem free for C bounce

#pragma unroll
    for (int j = 0; j < 8; j++)
        wmma::store_matrix_sync(Cf + (wid * 16) * LDC + j * 16, acc[j], LDC,
                                wmma::mem_row_major);
    __syncthreads();

    // convert C (fp32 smem) -> fp16 global; 2 threads per row
    {
        int r = tid >> 1;
        int c0 = (tid & 1) * 64;
        int gr = row0 + r;
        if (gr < NN) {
            const float* src = Cf + r * LDC + c0;
            __half* dst = g_hs + gr * FF + c0;
#pragma unroll
            for (int i = 0; i < 64; i += 8) {
                uint4 u;
                u.x = h2u(__floats2half2_rn(src[i + 0], src[i + 1]));
                u.y = h2u(__floats2half2_rn(src[i + 2], src[i + 3]));
                u.z = h2u(__floats2half2_rn(src[i + 4], src[i + 5]));
                u.w = h2u(__floats2half2_rn(src[i + 6], src[i + 7]));
                *(uint4*)(dst + i) = u;
            }
        }
    }
}

// ---------------- aggregation (fp16 gathers; fp32 accumulate; 4-way unrolled) -----
// agg[dst] = dinv[dst] * ( h[dst]*dinv[dst] + sum_src h[src]*dinv[src] )
__global__ __launch_bounds__(256) void k_agg() {
    int tid = threadIdx.x;
    int lane = tid & 31;
    int gw = (blockIdx.x * 256 + tid) >> 5;   // node id (1 warp per node)
    const uint2* b = (const uint2*)g_hs;      // row = 32 uint2 (4 halfs each)
    float dself = __ldg(&g_dinv[gw]);

    uint2 us = __ldg(&b[gw * 32 + lane]);
    float2 sf0 = u2f2(us.x), sf1 = u2f2(us.y);
    float4 a0 = {sf0.x * dself, sf0.y * dself, sf1.x * dself, sf1.y * dself};
    float4 a1 = {0.f, 0.f, 0.f, 0.f};
    float4 a2 = {0.f, 0.f, 0.f, 0.f};
    float4 a3 = {0.f, 0.f, 0.f, 0.f};

    int s = g_off[gw];
    int n = g_deg[gw];
    int e = s, end4 = s + (n & ~3);
    for (; e < end4; e += 4) {
        int s0 = __ldg(&g_csr[e + 0]);
        int s1 = __ldg(&g_csr[e + 1]);
        int s2 = __ldg(&g_csr[e + 2]);
        int s3 = __ldg(&g_csr[e + 3]);
        float d0 = __ldg(&g_dinv[s0]);
        float d1 = __ldg(&g_dinv[s1]);
        float d2 = __ldg(&g_dinv[s2]);
        float d3 = __ldg(&g_dinv[s3]);
        uint2 u0 = __ldg(&b[s0 * 32 + lane]);
        uint2 u1 = __ldg(&b[s1 * 32 + lane]);
        uint2 u2 = __ldg(&b[s2 * 32 + lane]);
        uint2 u3 = __ldg(&b[s3 * 32 + lane]);
        float2 f0a = u2f2(u0.x), f0b = u2f2(u0.y);
        float2 f1a = u2f2(u1.x), f1b = u2f2(u1.y);
        float2 f2a = u2f2(u2.x), f2b = u2f2(u2.y);
        float2 f3a = u2f2(u3.x), f3b = u2f2(u3.y);
        a0.x = fmaf(f0a.x, d0, a0.x); a0.y = fmaf(f0a.y, d0, a0.y);
        a0.z = fmaf(f0b.x, d0, a0.z); a0.w = fmaf(f0b.y, d0, a0.w);
        a1.x = fmaf(f1a.x, d1, a1.x); a1.y = fmaf(f1a.y, d1, a1.y);
        a1.z = fmaf(f1b.x, d1, a1.z); a1.w = fmaf(f1b.y, d1, a1.w);
        a2.x = fmaf(f2a.x, d2, a2.x); a2.y = fmaf(f2a.y, d2, a2.y);
        a2.z = fmaf(f2b.x, d2, a2.z); a2.w = fmaf(f2b.y, d2, a2.w);
        a3.x = fmaf(f3a.x, d3, a3.x); a3.y = fmaf(f3a.y, d3, a3.y);
        a3.z = fmaf(f3b.x, d3, a3.z); a3.w = fmaf(f3b.y, d3, a3.w);
    }
    for (; e < s + n; e++) {
        int s0 = __ldg(&g_csr[e]);
        float d0 = __ldg(&g_dinv[s0]);
        uint2 u0 = __ldg(&b[s0 * 32 + lane]);
        float2 f0a = u2f2(u0.x), f0b = u2f2(u0.y);
        a0.x = fmaf(f0a.x, d0, a0.x); a0.y = fmaf(f0a.y, d0, a0.y);
        a0.z = fmaf(f0b.x, d0, a0.z); a0.w = fmaf(f0b.y, d0, a0.w);
    }
    a0.x += a1.x + a2.x + a3.x;
    a0.y += a1.y + a2.y + a3.y;
    a0.z += a1.z + a2.z + a3.z;
    a0.w += a1.w + a2.w + a3.w;
    a0.x *= dself; a0.y *= dself; a0.z *= dself; a0.w *= dself;
    ((float4*)g_agg)[gw * 32 + lane] = a0;
}

// column sums / sumsq (proven; 102K atomics over 256 addrs)
__global__ __launch_bounds__(128) void k_reduce(float* __restrict__ stats) {
    int col = threadIdx.x;  // blockDim = 128
    int r0 = blockIdx.x * 125;
    int r1 = min(r0 + 125, NN);
    float s = 0.f, q = 0.f;
    for (int r = r0; r < r1; r++) {
        float v = g_agg[r * FF + col];
        s += v;
        q += v * v;
    }
    atomicAdd(&stats[col], s);
    atomicAdd(&stats[FF + col], q);
}

// BatchNorm (biased var) + PReLU for the final layer
__global__ __launch_bounds__(256) void k_norm(const float* __restrict__ stats,
                                              const float* __restrict__ gam,
                                              const float* __restrict__ bet,
                                              const float* __restrict__ aw,
                                              float* __restrict__ out) {
    int idx = blockIdx.x * blockDim.x + threadIdx.x;
    int c = (idx & 31) * 4;
    float4 v = ((const float4*)g_agg)[idx];
    float a = __ldg(&aw[0]);
    float vv[4] = {v.x, v.y, v.z, v.w};
    float o[4];
    const float invN = 1.f / (float)NN;
#pragma unroll
    for (int j = 0; j < 4; j++) {
        float mu  = stats[c + j] * invN;
        float var = stats[FF + c + j] * invN - mu * mu;
        float inv = rsqrtf(var + 1e-5f);
        float sc  = gam[c + j] * inv;
        float of  = bet[c + j] - mu * sc;
        float t = vv[j] * sc + of;
        o[j] = (t >= 0.f) ? t : a * t;
    }
    float4 r = {o[0], o[1], o[2], o[3]};
    ((float4*)out)[idx] = r;
}

// ---------------- eager load + cached device ptrs + fork stream (static init) ----
namespace {
float* p_agg = nullptr;
float* p_st1 = nullptr;
float* p_st2 = nullptr;
cudaStream_t s_fork = nullptr;
cudaEvent_t  ev_in = nullptr, ev_gemm = nullptr;
struct HxEagerLoad {
    HxEagerLoad() {
        void* p = nullptr;
        cudaGetSymbolAddress(&p, g_hs);    // triggers full module load
        cudaGetSymbolAddress(&p, g_csr);
        cudaGetSymbolAddress((void**)&p_agg, g_agg);
        cudaGetSymbolAddress((void**)&p_st1, g_stats1);
        cudaGetSymbolAddress((void**)&p_st2, g_stats2);
        cudaFuncSetAttribute(k_gemm, cudaFuncAttributeMaxDynamicSharedMemorySize,
                             GEMM_SMEM);
        cudaStreamCreateWithFlags(&s_fork, cudaStreamNonBlocking);
        cudaEventCreateWithFlags(&ev_in, cudaEventDisableTiming);
        cudaEventCreateWithFlags(&ev_gemm, cudaEventDisableTiming);
    }
};
HxEagerLoad hx_eager_load_;
}  // namespace

// ---------------- launch ----------------------------------------------------------
extern "C" void kernel_launch(void* const* d_in, const int* in_sizes, int n_in,
                              void* d_out, int out_size) {
    const float* x   = (const float*)d_in[0];
    const int*   ei  = (const int*)d_in[1];
    const float* W1  = (const float*)d_in[2];
    const float* gm1 = (const float*)d_in[4];
    const float* be1 = (const float*)d_in[5];
    const float* a1  = (const float*)d_in[6];
    const float* W2  = (const float*)d_in[7];
    const float* gm2 = (const float*)d_in[9];
    const float* be2 = (const float*)d_in[10];
    const float* a2  = (const float*)d_in[11];
    float* out = (float*)d_out;

    const int gemm_blocks = (NN + TM - 1) / TM;   // 391
    const int agg_blocks  = (NN * 32) / 256;      // 6250 exact
    const int red_blocks  = (NN + 124) / 125;     // 400

    // fork point: GEMM1 depends only on inputs, not the CSR build
    cudaEventRecord(ev_in, 0);
    cudaStreamWaitEvent(s_fork, ev_in, 0);

    // GEMM1 concurrent on forked stream
    k_gemm<<<gemm_blocks, 256, GEMM_SMEM, s_fork>>>(
        x, W1, nullptr, nullptr, nullptr, nullptr);
    cudaEventRecord(ev_gemm, s_fork);

    // CSR build chain (default stream)
    k_init<<<NBLK, SBLK>>>((const unsigned int*)ei);
    k_count<<<(EE + 255) / 256, 256>>>(ei);
    k_bsum<<<NBLK, SBLK>>>();
    k_offsets<<<NBLK, SBLK>>>();
    k_fill<<<(EE + 255) / 256, 256>>>(ei);

    cudaStreamWaitEvent(0, ev_gemm, 0);

    // join: layer-1 aggregation onward (default stream)
    k_agg<<<agg_blocks, 256>>>();
    k_reduce<<<red_blocks, 128>>>(p_st1);
    k_gemm<<<gemm_blocks, 256, GEMM_SMEM>>>(p_agg, W2,   // BN1+PReLU fused
                                            p_st1, gm1, be1, a1);
    k_agg<<<agg_blocks, 256>>>();
    k_reduce<<<red_blocks, 128>>>(p_st2);
    k_norm<<<agg_blocks, 256>>>(p_st2, gm2, be2, a2, out);
}